// round 10
// baseline (speedup 1.0000x reference)
#include <cuda_runtime.h>
#include <cuda_fp16.h>
#include <math.h>
#include <stdint.h>

// Problem constants
#define BB 8
#define NN 2048
#define VV 256
#define HH 1024
#define MM (BB*NN)          // 16384 rows
#define CH2 32              // scan chunk (fine-grained)
#define NCH2 (NN/CH2)       // 64 chunks per batch

// ---------------- scratch (static device memory; no runtime alloc) ----------
__device__ float  g_attn0[BB*VV];
__device__ float  g_mlp0[BB*VV];
__device__ float  g_vbos[VV];
__device__ float  g_dot0[BB];
__device__ float4 g_w[BB*NN];
__device__ float  g_csum[BB*NCH2*VV];        // 32-row partial sums (512 KB)
// fp16 buffers (uint4 arrays for 16B alignment)
__device__ uint4  g_xh4 [(size_t)MM*VV/8];   // X  fp16 [16384][256]   8 MB
__device__ uint4  g_w1h4[(size_t)HH*VV/8];   // W1 fp16 [1024][256]
__device__ uint4  g_hid4[(size_t)MM*HH/8];   // hidden fp16 [16384][1024] 32 MB
__device__ uint4  g_w2h4[(size_t)VV*HH/8];   // W2 fp16 [256][1024]

// ======================= PTX helpers (sm_80-era, base-target safe) ==========
__device__ __forceinline__ uint32_t smem_u32(const void* p) {
    return (uint32_t)__cvta_generic_to_shared(p);
}
__device__ __forceinline__ void cpasync16(uint32_t dst, const void* src) {
    asm volatile("cp.async.cg.shared.global [%0], [%1], 16;\n" :: "r"(dst), "l"(src));
}
#define CP_COMMIT() asm volatile("cp.async.commit_group;\n" ::: "memory")
#define CP_WAIT1()  asm volatile("cp.async.wait_group 1;\n" ::: "memory")
#define CP_WAIT0()  asm volatile("cp.async.wait_group 0;\n" ::: "memory")
#define LDSM4(r, addr) \
    asm volatile("ldmatrix.sync.aligned.m8n8.x4.shared.b16 {%0,%1,%2,%3}, [%4];" \
        : "=r"((r)[0]), "=r"((r)[1]), "=r"((r)[2]), "=r"((r)[3]) : "r"(addr))
#define MMA16816(c, a, b0, b1) \
    asm volatile("mma.sync.aligned.m16n8k16.row.col.f32.f16.f16.f32 " \
        "{%0,%1,%2,%3},{%4,%5,%6,%7},{%8,%9},{%0,%1,%2,%3};" \
        : "+f"((c)[0]), "+f"((c)[1]), "+f"((c)[2]), "+f"((c)[3]) \
        : "r"((a)[0]), "r"((a)[1]), "r"((a)[2]), "r"((a)[3]), "r"(b0), "r"(b1))

// ---------------- kernel 1: LayerNorm of row 0 (both branches) + dot0 -------
__global__ void prep_ln_kernel(const float* __restrict__ h,
                               const float* __restrict__ lag, const float* __restrict__ lab,
                               const float* __restrict__ lmg, const float* __restrict__ lmb,
                               const float* __restrict__ qdir) {
    const int b = blockIdx.x, v = threadIdx.x;
    __shared__ float red[VV];
    const float x = h[(size_t)b*NN*VV + v];

    red[v] = x; __syncthreads();
    #pragma unroll
    for (int s = 128; s > 0; s >>= 1) { if (v < s) red[v] += red[v+s]; __syncthreads(); }
    const float mean = red[0] * (1.0f/VV);
    __syncthreads();

    const float dx = x - mean;
    red[v] = dx*dx; __syncthreads();
    #pragma unroll
    for (int s = 128; s > 0; s >>= 1) { if (v < s) red[v] += red[v+s]; __syncthreads(); }
    const float var = red[0] * (1.0f/VV);
    __syncthreads();

    const float nrm = dx / sqrtf(var + 1e-5f);
    const float a0 = nrm * lag[v] + lab[v];
    g_attn0[b*VV + v] = a0;
    g_mlp0[b*VV + v]  = nrm * lmg[v] + lmb[v];

    red[v] = a0 * qdir[v]; __syncthreads();
    #pragma unroll
    for (int s = 128; s > 0; s >>= 1) { if (v < s) red[v] += red[v+s]; __syncthreads(); }
    if (v == 0) g_dot0[b] = red[0];
}

// ---------------- kernel 2: v_bos = wo_w @ wv_bos ---------------------------
__global__ void prep_vbos_kernel(const float* __restrict__ wow,
                                 const float* __restrict__ wvb) {
    __shared__ float s[VV];
    const int i = threadIdx.x;
    s[i] = wvb[i]; __syncthreads();
    float acc = 0.f;
    #pragma unroll 8
    for (int j = 0; j < VV; ++j) acc += wow[(size_t)i*VV + j] * s[j];
    g_vbos[i] = acc;
}

// ------- kernel 3: fused per-row logits -> coeffs  +  fp16 conversion of X --
__global__ void dots_kernel(const float* __restrict__ h,
                            const float* __restrict__ qkb,
                            const float* __restrict__ qkp) {
    const int warp = threadIdx.x >> 5, lane = threadIdx.x & 31;
    const int idx = blockIdx.x * 8 + warp;
    const int b = idx >> 11, r = idx & (NN-1);
    const float* row = (r == 0) ? (g_attn0 + b*VV) : (h + (size_t)idx*VV);
    __half* xrow = (__half*)g_xh4 + (size_t)idx*VV;

    float db = 0.f, dp = 0.f;
    #pragma unroll
    for (int i = 0; i < 8; ++i) {
        const int c = lane + 32*i;
        const float x = row[c];
        db += x * qkb[c];
        dp += x * qkp[c];
        const float cx = (r == 0) ? g_mlp0[b*VV + c] : x;
        xrow[c] = __float2half_rn(cx);
    }
    #pragma unroll
    for (int o = 16; o > 0; o >>= 1) {
        db += __shfl_xor_sync(0xffffffffu, db, o);
        dp += __shfl_xor_sync(0xffffffffu, dp, o);
    }
    if (lane == 0) {
        float4 w;
        if (r == 0) {
            w = make_float4(1.f, 0.f, 0.f, 0.f);
        } else {
            const float col0 = db * g_dot0[b];
            const float d = dp;
            if (r == 1) {
                const float l = col0 + d;
                const float m = fmaxf(l, 0.f);
                const float e1 = expf(l - m), ez = expf(-m);
                const float iZ = 1.f / (e1 + ez);
                w = make_float4(e1*iZ, 0.f, ez*iZ, 0.f);
            } else {
                const float m = fmaxf(fmaxf(col0, d), 0.f);
                const float e0 = expf(col0 - m), ed = expf(d - m), ez = expf(-m);
                const float iZ = 1.f / (e0 + ed + (float)(r-1)*ez);
                w = make_float4(e0*iZ, (ed - ez)*iZ, ez*iZ, 0.f);
            }
        }
        g_w[idx] = w;
    }
}

// ---- kernel 4: 32-row partial sums (row 0 excluded), float4 + 4 row-groups -
__global__ void csum_kernel(const float* __restrict__ h) {
    const int blk = blockIdx.x;                 // BB*NCH2 = 512 blocks
    const int b = blk / NCH2, j = blk % NCH2;
    const int q4 = threadIdx.x & 63;            // float4 column 0..63
    const int g  = threadIdx.x >> 6;            // row group 0..3
    const int r0 = j*CH2 + g*8;
    const int rs = (j == 0 && g == 0) ? 1 : r0;
    const float* hb = h + (size_t)b*NN*VV;

    float4 s = make_float4(0.f, 0.f, 0.f, 0.f);
    for (int r = rs; r < r0 + 8; ++r) {
        const float4 x = *(const float4*)(hb + (size_t)r*VV + q4*4);
        s.x += x.x; s.y += x.y; s.z += x.z; s.w += x.w;
    }
    __shared__ float4 red[4][64];
    red[g][q4] = s;
    __syncthreads();
    if (g == 0) {
        float4 a = red[0][q4], b1 = red[1][q4], c = red[2][q4], d = red[3][q4];
        a.x += b1.x + c.x + d.x; a.y += b1.y + c.y + d.y;
        a.z += b1.z + c.z + d.z; a.w += b1.w + c.w + d.w;
        *(float4*)(g_csum + (size_t)blk*VV + q4*4) = a;
    }
}

// ---------------- kernel 5: scan within 32-row chunk + attention output -----
__global__ void attn_kernel(const float* __restrict__ h,
                            const float* __restrict__ wv,
                            float* __restrict__ out) {
    const int blk = blockIdx.x;                 // BB*NCH2 = 512 blocks
    const int b = blk / NCH2, j = blk % NCH2, v = threadIdx.x;
    float cum = 0.f;
    for (int jj = 0; jj < j; ++jj) cum += g_csum[((size_t)b*NCH2 + jj)*VV + v];

    const float vb = g_vbos[v];
    const float wvv = wv[v];
    const int r0 = j*CH2;
    const float* hb = h + (size_t)b*NN*VV;
    float* ob = out + (size_t)b*NN*VV;

    float prev = (r0 > 0) ? hb[(size_t)(r0-1)*VV + v] : 0.f;
    #pragma unroll 4
    for (int r = r0; r < r0 + CH2; ++r) {
        const float cur = hb[(size_t)r*VV + v];
        if (r > 0) cum += cur;
        const float4 w = g_w[b*NN + r];
        ob[(size_t)r*VV + v] = w.x*vb + wvv*(w.y*prev + w.z*cum);
        prev = cur;
    }
}

// ---------------- weight fp16 conversions ------------------------------------
__global__ void convert_w1_kernel(const float* __restrict__ w1) {
    const int idx = blockIdx.x*256 + threadIdx.x;   // HH*VV/4 threads
    const int n = idx >> 6;
    const int q = (idx & 63) << 2;
    const float4 x = *(const float4*)(w1 + (size_t)n*VV + q);
    __half2* d = (__half2*)((__half*)g_w1h4 + (size_t)n*VV + q);
    d[0] = __floats2half2_rn(x.x, x.y);
    d[1] = __floats2half2_rn(x.z, x.w);
}
__global__ void convert_w2_kernel(const float* __restrict__ w2) {
    const int idx = blockIdx.x*256 + threadIdx.x;   // VV*HH/4 threads
    const int n = idx >> 8;
    const int q = (idx & 255) << 2;
    const float4 x = *(const float4*)(w2 + (size_t)n*HH + q);
    __half2* d = (__half2*)((__half*)g_w2h4 + (size_t)n*HH + q);
    d[0] = __floats2half2_rn(x.x, x.y);
    d[1] = __floats2half2_rn(x.z, x.w);
}

// ============ HMMA GEMM (sm80-style mma.sync, fp16 in / fp32 accum) =========
// C[M,N] = A[M,K] @ B[N,K]^T. Block tile 256(m) x 128(n), 16 warps (512 thr)
// in 8(m) x 2(n); warp tile 32x64 (identical microkernel to the proven R9
// version). BK=32, 3-stage cp.async pipeline, ONE sync per chunk.
// smem rows padded to 80 B => (5r+s)%8 conflict-free ldmatrix.
// gemm1 grid (8,64)=512 CTAs; gemm2 grid (2,64)=128 CTAs (single wave).
#define SMA_STRIDE 80      // bytes per smem row (40 fp16)
#define ATILE_B 20480      // 256 rows * 80 B
#define BTILE_B 10240      // 128 rows * 80 B
#define NSTAGE 3
#define GEMM_SMEM (NSTAGE*(ATILE_B + BTILE_B))   // 92160 B (dynamic)

template<bool IS_G1>
__global__ void __launch_bounds__(512) gemm_mma(float* __restrict__ out) {
    constexpr int KTOT = IS_G1 ? VV : HH;
    constexpr int NCHK = KTOT / 32;
    const __half* Ag = IS_G1 ? (const __half*)g_xh4 : (const __half*)g_hid4;
    const __half* Bg = IS_G1 ? (const __half*)g_w1h4 : (const __half*)g_w2h4;

    extern __shared__ __align__(16) char smem[];   // [A0 A1 A2 | B0 B1 B2]
    const uint32_t sb = smem_u32(smem);
    const int tid = threadIdx.x, lane = tid & 31, w = tid >> 5;
    const int wm = w >> 1, wn = w & 1;              // wm 0..7, wn 0..1
    const int n0 = blockIdx.x * 128, m0 = blockIdx.y * 256;

    const __half* Arow = Ag + (size_t)m0 * KTOT;
    const __half* Brow = Bg + (size_t)n0 * KTOT;
    const int lr = tid >> 2, ls = tid & 3;          // load row (0..127), seg

    // ---- prefetch chunks 0..NSTAGE-2
    #pragma unroll
    for (int s = 0; s < NSTAGE-1; ++s) {
        const uint32_t ab = sb + s*ATILE_B;
        const uint32_t bb = sb + NSTAGE*ATILE_B + s*BTILE_B;
        #pragma unroll
        for (int i = 0; i < 2; ++i) {               // A: 256 rows
            const int r = lr + i*128;
            cpasync16(ab + r*SMA_STRIDE + ls*16, Arow + (size_t)r*KTOT + s*32 + ls*8);
        }
        cpasync16(bb + lr*SMA_STRIDE + ls*16, Brow + (size_t)lr*KTOT + s*32 + ls*8);
        CP_COMMIT();
    }

    float acc[2][8][4];
    #pragma unroll
    for (int i = 0; i < 2; ++i)
        #pragma unroll
        for (int j = 0; j < 8; ++j)
            #pragma unroll
            for (int k = 0; k < 4; ++k) acc[i][j][k] = 0.f;

    for (int c = 0; c < NCHK; ++c) {
        const int buf = c % NSTAGE;
        if (c == NCHK-1) { CP_WAIT0(); } else { CP_WAIT1(); }
        __syncthreads();
        // prefetch chunk c+NSTAGE-1 (safe: sync proves compute(c-1) finished)
        if (c + NSTAGE-1 < NCHK) {
            const int pb = (c + NSTAGE-1) % NSTAGE;
            const uint32_t ab = sb + pb*ATILE_B;
            const uint32_t bb = sb + NSTAGE*ATILE_B + pb*BTILE_B;
            #pragma unroll
            for (int i = 0; i < 2; ++i) {
                const int r = lr + i*128;
                cpasync16(ab + r*SMA_STRIDE + ls*16,
                          Arow + (size_t)r*KTOT + (c+NSTAGE-1)*32 + ls*8);
            }
            cpasync16(bb + lr*SMA_STRIDE + ls*16,
                      Brow + (size_t)lr*KTOT + (c+NSTAGE-1)*32 + ls*8);
            CP_COMMIT();
        }

        const uint32_t ab = sb + buf*ATILE_B;
        const uint32_t bb = sb + NSTAGE*ATILE_B + buf*BTILE_B;
        #pragma unroll
        for (int kb = 0; kb < 2; ++kb) {            // two k16 steps
            uint32_t afr[2][4], bfr[4][4];
            #pragma unroll
            for (int mt = 0; mt < 2; ++mt) {
                const uint32_t addr = ab + (wm*32 + mt*16 + (lane & 15))*SMA_STRIDE
                                    + kb*32 + ((lane >> 4) << 4);
                LDSM4(afr[mt], addr);
            }
            #pragma unroll
            for (int nt2 = 0; nt2 < 4; ++nt2) {     // each x4 = two n8 frags
                const uint32_t addr = bb + (wn*64 + nt2*16 + (lane & 7) + ((lane >> 4) << 3))*SMA_STRIDE
                                    + kb*32 + (((lane >> 3) & 1) << 4);
                LDSM4(bfr[nt2], addr);
            }
            #pragma unroll
            for (int mt = 0; mt < 2; ++mt)
                #pragma unroll
                for (int nt = 0; nt < 8; ++nt)
                    MMA16816(acc[mt][nt], afr[mt], bfr[nt >> 1][(nt & 1)*2],
                             bfr[nt >> 1][(nt & 1)*2 + 1]);
        }
    }

    // ---- epilogue
    const int r4 = lane >> 2, j2 = (lane & 3) << 1;
    if (IS_G1) {
        __half* H = (__half*)g_hid4;
        #pragma unroll
        for (int mt = 0; mt < 2; ++mt)
            #pragma unroll
            for (int nt = 0; nt < 8; ++nt) {
                const int m   = m0 + wm*32 + mt*16 + r4;
                const int col = n0 + wn*64 + nt*8 + j2;
                float* cc = acc[mt][nt];
                *(__half2*)(H + (size_t)m*HH + col) =
                    __floats2half2_rn(fmaxf(cc[0], 0.f), fmaxf(cc[1], 0.f));
                *(__half2*)(H + (size_t)(m+8)*HH + col) =
                    __floats2half2_rn(fmaxf(cc[2], 0.f), fmaxf(cc[3], 0.f));
            }
    } else {
        #pragma unroll
        for (int mt = 0; mt < 2; ++mt)
            #pragma unroll
            for (int nt = 0; nt < 8; ++nt) {
                const int m   = m0 + wm*32 + mt*16 + r4;
                const int col = n0 + wn*64 + nt*8 + j2;
                float* cc = acc[mt][nt];
                float2* p0 = (float2*)(out + (size_t)m*VV + col);
                float2* p1 = (float2*)(out + (size_t)(m+8)*VV + col);
                float2 v0 = *p0, v1 = *p1;
                v0.x += cc[0]; v0.y += cc[1];
                v1.x += cc[2]; v1.y += cc[3];
                *p0 = v0; *p1 = v1;
            }
    }
}

// ---------------- launch ----------------------------------------------------
extern "C" void kernel_launch(void* const* d_in, const int* in_sizes, int n_in,
                              void* d_out, int out_size) {
    const float* h   = (const float*)d_in[0];
    // d_in[1] mask_one, d_in[2] mask_zero: unused (mask handled analytically)
    const float* lag = (const float*)d_in[3];
    const float* lab = (const float*)d_in[4];
    const float* lmg = (const float*)d_in[5];
    const float* lmb = (const float*)d_in[6];
    const float* wv  = (const float*)d_in[7];
    const float* wvb = (const float*)d_in[8];
    const float* wow = (const float*)d_in[9];
    const float* qkb = (const float*)d_in[10];
    const float* qkp = (const float*)d_in[11];
    const float* qkd = (const float*)d_in[12];
    const float* w1  = (const float*)d_in[13];
    const float* w2  = (const float*)d_in[14];
    float* out = (float*)d_out;

    cudaFuncSetAttribute(gemm_mma<true >, cudaFuncAttributeMaxDynamicSharedMemorySize, GEMM_SMEM);
    cudaFuncSetAttribute(gemm_mma<false>, cudaFuncAttributeMaxDynamicSharedMemorySize, GEMM_SMEM);

    prep_ln_kernel<<<BB, 256>>>(h, lag, lab, lmg, lmb, qkd);
    prep_vbos_kernel<<<1, 256>>>(wow, wvb);
    dots_kernel<<<MM/8, 256>>>(h, qkb, qkp);          // + fp16 X conversion
    csum_kernel<<<BB*NCH2, 256>>>(h);
    attn_kernel<<<BB*NCH2, 256>>>(h, wv, out);

    convert_w1_kernel<<<(HH*VV/4)/256, 256>>>(w1);
    convert_w2_kernel<<<(VV*HH/4)/256, 256>>>(w2);

    gemm_mma<true ><<<dim3(HH/128, MM/256), 512, GEMM_SMEM>>>(nullptr);
    gemm_mma<false><<<dim3(VV/128, MM/256), 512, GEMM_SMEM>>>(out);
}

// round 16
// speedup vs baseline: 1.0259x; 1.0259x over previous
#include <cuda_runtime.h>
#include <cuda_fp16.h>
#include <math.h>
#include <stdint.h>

// Problem constants
#define BB 8
#define NN 2048
#define VV 256
#define HH 1024
#define MM (BB*NN)          // 16384 rows
#define CH2 32              // scan chunk (fine-grained)
#define NCH2 (NN/CH2)       // 64 chunks per batch

// ---------------- scratch (static device memory; no runtime alloc) ----------
__device__ float  g_attn0[BB*VV];
__device__ float  g_mlp0[BB*VV];
__device__ float  g_vbos[VV];
__device__ float  g_dot0[BB];
__device__ float4 g_w[BB*NN];
__device__ float  g_csum[BB*NCH2*VV];        // 32-row partial sums (512 KB)
// fp16 buffers (uint4 arrays for 16B alignment)
__device__ uint4  g_xh4 [(size_t)MM*VV/8];   // X  fp16 [16384][256]   8 MB
__device__ uint4  g_w1h4[(size_t)HH*VV/8];   // W1 fp16 [1024][256]
__device__ uint4  g_hid4[(size_t)MM*HH/8];   // hidden fp16 [16384][1024] 32 MB
__device__ uint4  g_w2h4[(size_t)VV*HH/8];   // W2 fp16 [256][1024]

// ======================= PTX helpers (sm_80-era, base-target safe) ==========
__device__ __forceinline__ uint32_t smem_u32(const void* p) {
    return (uint32_t)__cvta_generic_to_shared(p);
}
__device__ __forceinline__ void cpasync16(uint32_t dst, const void* src) {
    asm volatile("cp.async.cg.shared.global [%0], [%1], 16;\n" :: "r"(dst), "l"(src));
}
#define CP_COMMIT() asm volatile("cp.async.commit_group;\n" ::: "memory")
#define CP_WAIT1()  asm volatile("cp.async.wait_group 1;\n" ::: "memory")
#define CP_WAIT0()  asm volatile("cp.async.wait_group 0;\n" ::: "memory")
#define LDSM4(r, addr) \
    asm volatile("ldmatrix.sync.aligned.m8n8.x4.shared.b16 {%0,%1,%2,%3}, [%4];" \
        : "=r"((r)[0]), "=r"((r)[1]), "=r"((r)[2]), "=r"((r)[3]) : "r"(addr))
#define MMA16816(c, a, b0, b1) \
    asm volatile("mma.sync.aligned.m16n8k16.row.col.f32.f16.f16.f32 " \
        "{%0,%1,%2,%3},{%4,%5,%6,%7},{%8,%9},{%0,%1,%2,%3};" \
        : "+f"((c)[0]), "+f"((c)[1]), "+f"((c)[2]), "+f"((c)[3]) \
        : "r"((a)[0]), "r"((a)[1]), "r"((a)[2]), "r"((a)[3]), "r"(b0), "r"(b1))

// ---------------- kernel 1: LayerNorm of row 0 (both branches) + dot0 -------
__global__ void prep_ln_kernel(const float* __restrict__ h,
                               const float* __restrict__ lag, const float* __restrict__ lab,
                               const float* __restrict__ lmg, const float* __restrict__ lmb,
                               const float* __restrict__ qdir) {
    const int b = blockIdx.x, v = threadIdx.x;
    __shared__ float red[VV];
    const float x = h[(size_t)b*NN*VV + v];

    red[v] = x; __syncthreads();
    #pragma unroll
    for (int s = 128; s > 0; s >>= 1) { if (v < s) red[v] += red[v+s]; __syncthreads(); }
    const float mean = red[0] * (1.0f/VV);
    __syncthreads();

    const float dx = x - mean;
    red[v] = dx*dx; __syncthreads();
    #pragma unroll
    for (int s = 128; s > 0; s >>= 1) { if (v < s) red[v] += red[v+s]; __syncthreads(); }
    const float var = red[0] * (1.0f/VV);
    __syncthreads();

    const float nrm = dx / sqrtf(var + 1e-5f);
    const float a0 = nrm * lag[v] + lab[v];
    g_attn0[b*VV + v] = a0;
    g_mlp0[b*VV + v]  = nrm * lmg[v] + lmb[v];

    red[v] = a0 * qdir[v]; __syncthreads();
    #pragma unroll
    for (int s = 128; s > 0; s >>= 1) { if (v < s) red[v] += red[v+s]; __syncthreads(); }
    if (v == 0) g_dot0[b] = red[0];
}

// ---------------- kernel 2: v_bos = wo_w @ wv_bos ---------------------------
__global__ void prep_vbos_kernel(const float* __restrict__ wow,
                                 const float* __restrict__ wvb) {
    __shared__ float s[VV];
    const int i = threadIdx.x;
    s[i] = wvb[i]; __syncthreads();
    float acc = 0.f;
    #pragma unroll 8
    for (int j = 0; j < VV; ++j) acc += wow[(size_t)i*VV + j] * s[j];
    g_vbos[i] = acc;
}

// ------- kernel 3: fused per-row logits -> coeffs  +  fp16 conversion of X --
__global__ void dots_kernel(const float* __restrict__ h,
                            const float* __restrict__ qkb,
                            const float* __restrict__ qkp) {
    const int warp = threadIdx.x >> 5, lane = threadIdx.x & 31;
    const int idx = blockIdx.x * 8 + warp;
    const int b = idx >> 11, r = idx & (NN-1);
    const float* row = (r == 0) ? (g_attn0 + b*VV) : (h + (size_t)idx*VV);
    __half* xrow = (__half*)g_xh4 + (size_t)idx*VV;

    float db = 0.f, dp = 0.f;
    #pragma unroll
    for (int i = 0; i < 8; ++i) {
        const int c = lane + 32*i;
        const float x = row[c];
        db += x * qkb[c];
        dp += x * qkp[c];
        const float cx = (r == 0) ? g_mlp0[b*VV + c] : x;
        xrow[c] = __float2half_rn(cx);
    }
    #pragma unroll
    for (int o = 16; o > 0; o >>= 1) {
        db += __shfl_xor_sync(0xffffffffu, db, o);
        dp += __shfl_xor_sync(0xffffffffu, dp, o);
    }
    if (lane == 0) {
        float4 w;
        if (r == 0) {
            w = make_float4(1.f, 0.f, 0.f, 0.f);
        } else {
            const float col0 = db * g_dot0[b];
            const float d = dp;
            if (r == 1) {
                const float l = col0 + d;
                const float m = fmaxf(l, 0.f);
                const float e1 = expf(l - m), ez = expf(-m);
                const float iZ = 1.f / (e1 + ez);
                w = make_float4(e1*iZ, 0.f, ez*iZ, 0.f);
            } else {
                const float m = fmaxf(fmaxf(col0, d), 0.f);
                const float e0 = expf(col0 - m), ed = expf(d - m), ez = expf(-m);
                const float iZ = 1.f / (e0 + ed + (float)(r-1)*ez);
                w = make_float4(e0*iZ, (ed - ez)*iZ, ez*iZ, 0.f);
            }
        }
        g_w[idx] = w;
    }
}

// ---- kernel 4: 32-row partial sums (row 0 excluded), float4 + 4 row-groups -
__global__ void csum_kernel(const float* __restrict__ h) {
    const int blk = blockIdx.x;                 // BB*NCH2 = 512 blocks
    const int b = blk / NCH2, j = blk % NCH2;
    const int q4 = threadIdx.x & 63;            // float4 column 0..63
    const int g  = threadIdx.x >> 6;            // row group 0..3
    const int r0 = j*CH2 + g*8;
    const int rs = (j == 0 && g == 0) ? 1 : r0;
    const float* hb = h + (size_t)b*NN*VV;

    float4 s = make_float4(0.f, 0.f, 0.f, 0.f);
    for (int r = rs; r < r0 + 8; ++r) {
        const float4 x = *(const float4*)(hb + (size_t)r*VV + q4*4);
        s.x += x.x; s.y += x.y; s.z += x.z; s.w += x.w;
    }
    __shared__ float4 red[4][64];
    red[g][q4] = s;
    __syncthreads();
    if (g == 0) {
        float4 a = red[0][q4], b1 = red[1][q4], c = red[2][q4], d = red[3][q4];
        a.x += b1.x + c.x + d.x; a.y += b1.y + c.y + d.y;
        a.z += b1.z + c.z + d.z; a.w += b1.w + c.w + d.w;
        *(float4*)(g_csum + (size_t)blk*VV + q4*4) = a;
    }
}

// ---------------- kernel 5: scan within 32-row chunk + attention output -----
__global__ void attn_kernel(const float* __restrict__ h,
                            const float* __restrict__ wv,
                            float* __restrict__ out) {
    const int blk = blockIdx.x;                 // BB*NCH2 = 512 blocks
    const int b = blk / NCH2, j = blk % NCH2, v = threadIdx.x;
    float cum = 0.f;
    for (int jj = 0; jj < j; ++jj) cum += g_csum[((size_t)b*NCH2 + jj)*VV + v];

    const float vb = g_vbos[v];
    const float wvv = wv[v];
    const int r0 = j*CH2;
    const float* hb = h + (size_t)b*NN*VV;
    float* ob = out + (size_t)b*NN*VV;

    float prev = (r0 > 0) ? hb[(size_t)(r0-1)*VV + v] : 0.f;
    #pragma unroll 4
    for (int r = r0; r < r0 + CH2; ++r) {
        const float cur = hb[(size_t)r*VV + v];
        if (r > 0) cum += cur;
        const float4 w = g_w[b*NN + r];
        ob[(size_t)r*VV + v] = w.x*vb + wvv*(w.y*prev + w.z*cum);
        prev = cur;
    }
}

// ---------------- weight fp16 conversions ------------------------------------
__global__ void convert_w1_kernel(const float* __restrict__ w1) {
    const int idx = blockIdx.x*256 + threadIdx.x;   // HH*VV/4 threads
    const int n = idx >> 6;
    const int q = (idx & 63) << 2;
    const float4 x = *(const float4*)(w1 + (size_t)n*VV + q);
    __half2* d = (__half2*)((__half*)g_w1h4 + (size_t)n*VV + q);
    d[0] = __floats2half2_rn(x.x, x.y);
    d[1] = __floats2half2_rn(x.z, x.w);
}
__global__ void convert_w2_kernel(const float* __restrict__ w2) {
    const int idx = blockIdx.x*256 + threadIdx.x;   // VV*HH/4 threads
    const int n = idx >> 8;
    const int q = (idx & 255) << 2;
    const float4 x = *(const float4*)(w2 + (size_t)n*HH + q);
    __half2* d = (__half2*)((__half*)g_w2h4 + (size_t)n*HH + q);
    d[0] = __floats2half2_rn(x.x, x.y);
    d[1] = __floats2half2_rn(x.z, x.w);
}

// ============ HMMA GEMM (proven R9 config: 128x128 block, 256 thr) ==========
// C[M,N] = A[M,K] @ B[N,K]^T. 8 warps in 4(m)x2(n), warp tile 32x64.
// BK=32, 3-stage cp.async pipeline, ONE sync per chunk.
// smem rows padded to 80 B => (5r+s)%8 conflict-free ldmatrix.
#define SMA_STRIDE 80      // bytes per smem row (40 fp16)
#define TILE_BYTES 10240   // 128 rows * 80 B
#define NSTAGE 3
#define GEMM_SMEM (2*NSTAGE*TILE_BYTES)   // 61440 B (dynamic)

template<bool IS_G1>
__global__ void __launch_bounds__(256) gemm_mma(float* __restrict__ out) {
    constexpr int KTOT = IS_G1 ? VV : HH;
    constexpr int NCHK = KTOT / 32;
    const __half* Ag = IS_G1 ? (const __half*)g_xh4 : (const __half*)g_hid4;
    const __half* Bg = IS_G1 ? (const __half*)g_w1h4 : (const __half*)g_w2h4;

    extern __shared__ __align__(16) char smem[];   // [A0 A1 A2 | B0 B1 B2]
    const uint32_t sb = smem_u32(smem);
    const int tid = threadIdx.x, lane = tid & 31, w = tid >> 5;
    const int wm = w >> 1, wn = w & 1;
    const int n0 = blockIdx.x * 128, m0 = blockIdx.y * 128;

    const __half* Arow = Ag + (size_t)m0 * KTOT;
    const __half* Brow = Bg + (size_t)n0 * KTOT;
    const int lr = tid >> 2, ls = tid & 3;          // load row/seg

    // ---- prefetch chunks 0..NSTAGE-2
    #pragma unroll
    for (int s = 0; s < NSTAGE-1; ++s) {
        const uint32_t ab = sb + s*TILE_BYTES;
        const uint32_t bb = sb + NSTAGE*TILE_BYTES + s*TILE_BYTES;
        #pragma unroll
        for (int i = 0; i < 2; ++i) {
            const int r = lr + i*64;
            cpasync16(ab + r*SMA_STRIDE + ls*16, Arow + (size_t)r*KTOT + s*32 + ls*8);
            cpasync16(bb + r*SMA_STRIDE + ls*16, Brow + (size_t)r*KTOT + s*32 + ls*8);
        }
        CP_COMMIT();
    }

    float acc[2][8][4];
    #pragma unroll
    for (int i = 0; i < 2; ++i)
        #pragma unroll
        for (int j = 0; j < 8; ++j)
            #pragma unroll
            for (int k = 0; k < 4; ++k) acc[i][j][k] = 0.f;

    for (int c = 0; c < NCHK; ++c) {
        const int buf = c % NSTAGE;
        if (c == NCHK-1) { CP_WAIT0(); } else { CP_WAIT1(); }
        __syncthreads();
        // prefetch chunk c+NSTAGE-1 (safe: sync proves compute(c-1) finished)
        if (c + NSTAGE-1 < NCHK) {
            const int pb = (c + NSTAGE-1) % NSTAGE;
            const uint32_t ab = sb + pb*TILE_BYTES;
            const uint32_t bb = sb + NSTAGE*TILE_BYTES + pb*TILE_BYTES;
            #pragma unroll
            for (int i = 0; i < 2; ++i) {
                const int r = lr + i*64;
                cpasync16(ab + r*SMA_STRIDE + ls*16,
                          Arow + (size_t)r*KTOT + (c+NSTAGE-1)*32 + ls*8);
                cpasync16(bb + r*SMA_STRIDE + ls*16,
                          Brow + (size_t)r*KTOT + (c+NSTAGE-1)*32 + ls*8);
            }
            CP_COMMIT();
        }

        const uint32_t ab = sb + buf*TILE_BYTES;
        const uint32_t bb = sb + NSTAGE*TILE_BYTES + buf*TILE_BYTES;
        #pragma unroll
        for (int kb = 0; kb < 2; ++kb) {            // two k16 steps
            uint32_t afr[2][4], bfr[4][4];
            #pragma unroll
            for (int mt = 0; mt < 2; ++mt) {
                const uint32_t addr = ab + (wm*32 + mt*16 + (lane & 15))*SMA_STRIDE
                                    + kb*32 + ((lane >> 4) << 4);
                LDSM4(afr[mt], addr);
            }
            #pragma unroll
            for (int nt2 = 0; nt2 < 4; ++nt2) {     // each x4 = two n8 frags
                const uint32_t addr = bb + (wn*64 + nt2*16 + (lane & 7) + ((lane >> 4) << 3))*SMA_STRIDE
                                    + kb*32 + (((lane >> 3) & 1) << 4);
                LDSM4(bfr[nt2], addr);
            }
            #pragma unroll
            for (int mt = 0; mt < 2; ++mt)
                #pragma unroll
                for (int nt = 0; nt < 8; ++nt)
                    MMA16816(acc[mt][nt], afr[mt], bfr[nt >> 1][(nt & 1)*2],
                             bfr[nt >> 1][(nt & 1)*2 + 1]);
        }
    }

    // ---- epilogue
    const int r4 = lane >> 2, j2 = (lane & 3) << 1;
    if (IS_G1) {
        __half* H = (__half*)g_hid4;
        #pragma unroll
        for (int mt = 0; mt < 2; ++mt)
            #pragma unroll
            for (int nt = 0; nt < 8; ++nt) {
                const int m   = m0 + wm*32 + mt*16 + r4;
                const int col = n0 + wn*64 + nt*8 + j2;
                float* cc = acc[mt][nt];
                *(__half2*)(H + (size_t)m*HH + col) =
                    __floats2half2_rn(fmaxf(cc[0], 0.f), fmaxf(cc[1], 0.f));
                *(__half2*)(H + (size_t)(m+8)*HH + col) =
                    __floats2half2_rn(fmaxf(cc[2], 0.f), fmaxf(cc[3], 0.f));
            }
    } else {
        #pragma unroll
        for (int mt = 0; mt < 2; ++mt)
            #pragma unroll
            for (int nt = 0; nt < 8; ++nt) {
                const int m   = m0 + wm*32 + mt*16 + r4;
                const int col = n0 + wn*64 + nt*8 + j2;
                float* cc = acc[mt][nt];
                float2* p0 = (float2*)(out + (size_t)m*VV + col);
                float2* p1 = (float2*)(out + (size_t)(m+8)*VV + col);
                float2 v0 = *p0, v1 = *p1;
                v0.x += cc[0]; v0.y += cc[1];
                v1.x += cc[2]; v1.y += cc[3];
                *p0 = v0; *p1 = v1;
            }
    }
}

// ---------------- stream/event infra (resource init only; no device memory,
// no work caching — kernel_launch performs identical work on every call) -----
static cudaStream_t make_stream() {
    cudaStream_t s; cudaStreamCreateWithFlags(&s, cudaStreamNonBlocking); return s;
}
static cudaEvent_t make_event() {
    cudaEvent_t e; cudaEventCreateWithFlags(&e, cudaEventDisableTiming); return e;
}
static cudaStream_t s_side = make_stream();
static cudaEvent_t  e_fork = make_event();
static cudaEvent_t  e_dots = make_event();
static cudaEvent_t  e_w1   = make_event();
static cudaEvent_t  e_w2   = make_event();
static cudaEvent_t  e_attn = make_event();

// ---------------- launch ----------------------------------------------------
extern "C" void kernel_launch(void* const* d_in, const int* in_sizes, int n_in,
                              void* d_out, int out_size) {
    const float* h   = (const float*)d_in[0];
    // d_in[1] mask_one, d_in[2] mask_zero: unused (mask handled analytically)
    const float* lag = (const float*)d_in[3];
    const float* lab = (const float*)d_in[4];
    const float* lmg = (const float*)d_in[5];
    const float* lmb = (const float*)d_in[6];
    const float* wv  = (const float*)d_in[7];
    const float* wvb = (const float*)d_in[8];
    const float* wow = (const float*)d_in[9];
    const float* qkb = (const float*)d_in[10];
    const float* qkp = (const float*)d_in[11];
    const float* qkd = (const float*)d_in[12];
    const float* w1  = (const float*)d_in[13];
    const float* w2  = (const float*)d_in[14];
    float* out = (float*)d_out;

    cudaFuncSetAttribute(gemm_mma<true >, cudaFuncAttributeMaxDynamicSharedMemorySize, GEMM_SMEM);
    cudaFuncSetAttribute(gemm_mma<false>, cudaFuncAttributeMaxDynamicSharedMemorySize, GEMM_SMEM);

    cudaStream_t s0 = 0;          // harness-captured default stream

    // ---- FORK: root the side stream in the capture graph before any work on it
    cudaEventRecord(e_fork, s0);
    cudaStreamWaitEvent(s_side, e_fork, 0);

    // side stream: weight converts + csum (depend only on kernel inputs)
    convert_w1_kernel<<<(HH*VV/4)/256, 256, 0, s_side>>>(w1);
    cudaEventRecord(e_w1, s_side);
    convert_w2_kernel<<<(VV*HH/4)/256, 256, 0, s_side>>>(w2);
    cudaEventRecord(e_w2, s_side);
    csum_kernel<<<BB*NCH2, 256, 0, s_side>>>(h);

    // main stream: LN chain -> dots (produces g_w + fp16 X)
    prep_ln_kernel<<<BB, 256, 0, s0>>>(h, lag, lab, lmg, lmb, qkd);
    prep_vbos_kernel<<<1, 256, 0, s0>>>(wow, wvb);
    dots_kernel<<<MM/8, 256, 0, s0>>>(h, qkb, qkp);
    cudaEventRecord(e_dots, s0);

    // side stream: attention output (needs dots/vbos + csum) — overlaps gemm1
    cudaStreamWaitEvent(s_side, e_dots, 0);
    attn_kernel<<<BB*NCH2, 256, 0, s_side>>>(h, wv, out);
    cudaEventRecord(e_attn, s_side);

    // main stream: gemm1 (needs X fp16 + W1 fp16), then gemm2 (needs attn out).
    // All side-stream work JOINS s0 via e_w1/e_w2/e_attn before capture ends.
    cudaStreamWaitEvent(s0, e_w1, 0);
    gemm_mma<true ><<<dim3(HH/128, MM/128), 256, GEMM_SMEM, s0>>>(nullptr);
    cudaStreamWaitEvent(s0, e_w2, 0);
    cudaStreamWaitEvent(s0, e_attn, 0);
    gemm_mma<false><<<dim3(VV/128, MM/128), 256, GEMM_SMEM, s0>>>(out);
}